// round 6
// baseline (speedup 1.0000x reference)
#include <cuda_runtime.h>
#include <cuda_bf16.h>
#include <cstdint>

#define Bsz 8
#define Dd  1024
#define Ls  1024
#define NH  8
#define DK  128
#define NEGV (-1e30f)

// -------------------- scratch (device globals; no allocation) --------------------
__device__ float g_q  [(size_t)Bsz * NH * Ls * DK];        // [B,H,L,DK]  32MB
__device__ float g_k  [(size_t)Bsz * NH * Ls * DK];        // 32MB
__device__ float g_v  [(size_t)Bsz * NH * Ls * DK];        // 32MB
__device__ float g_s  [(size_t)Bsz * NH * Ls * Ls];        // E = exp(S)  256MB
__device__ float g_ci [(size_t)Bsz * NH * Ls];             // col sums -> 1/sum
__device__ float g_hd [(size_t)Bsz * Ls * (NH * DK)];      // [B,L,H*DK]  32MB

// ==================== tf32 mma GEMM: 128x128 tile, BK=16, 256 threads ====================
#define BM 128
#define BN 128
#define BK 16
#define LDT 132   // smem row stride (uint32 units)

__device__ __forceinline__ uint32_t f2tf(float f) {
    uint32_t u;
    asm("cvt.rna.tf32.f32 %0, %1;" : "=r"(u) : "f"(f));
    return u;
}

__device__ __forceinline__ void mma_tf32(float c[4], const uint32_t a[4], const uint32_t b[2]) {
    asm volatile(
        "mma.sync.aligned.m16n8k8.row.col.f32.tf32.tf32.f32 "
        "{%0,%1,%2,%3}, {%4,%5,%6,%7}, {%8,%9}, {%0,%1,%2,%3};"
        : "+f"(c[0]), "+f"(c[1]), "+f"(c[2]), "+f"(c[3])
        : "r"(a[0]), "r"(a[1]), "r"(a[2]), "r"(a[3]), "r"(b[0]), "r"(b[1]));
}

// AMODE: 0 = A row-major [M][lda]; 1 = A stored [K][ldm] (contract rows)
// BMODE: 0 = B row-major [K][ldb]; 1 = B stored [N][ldn] (contract cols); 2 = 0 scaled by gi[k]

template <int AMODE>
__device__ __forceinline__ void ldgA(float4 r[2], const float* __restrict__ A,
                                     int lda, int row0, int k0)
{
    const int t = threadIdx.x;
    #pragma unroll
    for (int it = 0; it < 2; it++) {
        int idx = t + it * 256;
        if (AMODE == 1) {
            int k = idx >> 5, m4 = (idx & 31) << 2;
            r[it] = *(const float4*)&A[(size_t)(k0 + k) * lda + row0 + m4];
        } else {
            int m = idx >> 2, c4 = (idx & 3) << 2;
            r[it] = *(const float4*)&A[(size_t)(row0 + m) * lda + k0 + c4];
        }
    }
}

template <int AMODE>
__device__ __forceinline__ void stsA(uint32_t (*As)[LDT], const float4 r[2])
{
    const int t = threadIdx.x;
    #pragma unroll
    for (int it = 0; it < 2; it++) {
        int idx = t + it * 256;
        if (AMODE == 1) {
            int k = idx >> 5, m4 = (idx & 31) << 2;
            uint4 u = { f2tf(r[it].x), f2tf(r[it].y), f2tf(r[it].z), f2tf(r[it].w) };
            *(uint4*)&As[k][m4] = u;
        } else {
            int m = idx >> 2, c4 = (idx & 3) << 2;
            As[c4 + 0][m] = f2tf(r[it].x);
            As[c4 + 1][m] = f2tf(r[it].y);
            As[c4 + 2][m] = f2tf(r[it].z);
            As[c4 + 3][m] = f2tf(r[it].w);
        }
    }
}

template <int BMODE>
__device__ __forceinline__ void ldgB(float4 r[2], float s[2], const float* __restrict__ B,
                                     int ldb, int col0, int k0, const float* __restrict__ gi)
{
    const int t = threadIdx.x;
    #pragma unroll
    for (int it = 0; it < 2; it++) {
        int idx = t + it * 256;
        if (BMODE == 1) {
            int n = idx >> 2, c4 = (idx & 3) << 2;
            r[it] = *(const float4*)&B[(size_t)(col0 + n) * ldb + k0 + c4];
        } else {
            int k = idx >> 5, n4 = (idx & 31) << 2;
            r[it] = *(const float4*)&B[(size_t)(k0 + k) * ldb + col0 + n4];
            if (BMODE == 2) s[it] = __ldg(&gi[k0 + k]);
        }
    }
}

template <int BMODE>
__device__ __forceinline__ void stsB(uint32_t (*Bs)[LDT], const float4 r[2], const float s[2])
{
    const int t = threadIdx.x;
    #pragma unroll
    for (int it = 0; it < 2; it++) {
        int idx = t + it * 256;
        if (BMODE == 1) {
            int n = idx >> 2, c4 = (idx & 3) << 2;
            Bs[c4 + 0][n] = f2tf(r[it].x);
            Bs[c4 + 1][n] = f2tf(r[it].y);
            Bs[c4 + 2][n] = f2tf(r[it].z);
            Bs[c4 + 3][n] = f2tf(r[it].w);
        } else {
            int k = idx >> 5, n4 = (idx & 31) << 2;
            float4 v = r[it];
            if (BMODE == 2) { v.x *= s[it]; v.y *= s[it]; v.z *= s[it]; v.w *= s[it]; }
            uint4 u = { f2tf(v.x), f2tf(v.y), f2tf(v.z), f2tf(v.w) };
            *(uint4*)&Bs[k][n4] = u;
        }
    }
}

// Double-buffered mainloop. Warp tile 64x32 (2x4 warp grid), acc[4][4][4].
template <int AMODE, int BMODE>
__device__ __forceinline__ void gemm_main(
    const float* __restrict__ A, int lda,
    const float* __restrict__ B, int ldb,
    int Kdim, int row0, int col0,
    const float* __restrict__ gi,
    float acc[4][4][4])
{
    __shared__ uint32_t As[2][BK][LDT];
    __shared__ uint32_t Bs[2][BK][LDT];

    const int lane = threadIdx.x & 31;
    const int wid  = threadIdx.x >> 5;
    const int wm   = wid & 1;
    const int wn   = wid >> 1;
    const int r    = lane >> 2;
    const int c2   = (lane & 3) << 1;

    float4 ra[2], rb[2];
    float  rs[2];

    ldgA<AMODE>(ra, A, lda, row0, 0);
    ldgB<BMODE>(rb, rs, B, ldb, col0, 0, gi);
    stsA<AMODE>(As[0], ra);
    stsB<BMODE>(Bs[0], rb, rs);
    __syncthreads();

    const int nk = Kdim / BK;
    for (int i = 0; i < nk; i++) {
        const int cur = i & 1;
        if (i + 1 < nk) {
            ldgA<AMODE>(ra, A, lda, row0, (i + 1) * BK);
            ldgB<BMODE>(rb, rs, B, ldb, col0, (i + 1) * BK, gi);
        }

        #pragma unroll
        for (int ks = 0; ks < 2; ks++) {
            const int kb = ks * 8 + c2;
            uint32_t af[4][4], bf[4][2];
            #pragma unroll
            for (int mt = 0; mt < 4; mt++) {
                int ms = wm * 64 + mt * 16 + r;
                af[mt][0] = As[cur][kb][ms];
                af[mt][1] = As[cur][kb][ms + 8];
                af[mt][2] = As[cur][kb + 1][ms];
                af[mt][3] = As[cur][kb + 1][ms + 8];
            }
            #pragma unroll
            for (int nt = 0; nt < 4; nt++) {
                int ns = wn * 32 + nt * 8 + r;
                bf[nt][0] = Bs[cur][kb][ns];
                bf[nt][1] = Bs[cur][kb + 1][ns];
            }
            #pragma unroll
            for (int mt = 0; mt < 4; mt++)
                #pragma unroll
                for (int nt = 0; nt < 4; nt++)
                    mma_tf32(acc[mt][nt], af[mt], bf[nt]);
        }

        if (i + 1 < nk) {
            stsA<AMODE>(As[cur ^ 1], ra);
            stsB<BMODE>(Bs[cur ^ 1], rb, rs);
            __syncthreads();
        }
    }
}

// ==================== kernels ====================

// proj: q/k/v[b,h,l,dk] = sum_d x[b,d,l] * W[h,d,dk]
__global__ void __launch_bounds__(256, 2)
proj_kernel(const float* __restrict__ x,
            const float* __restrict__ Wq, const float* __restrict__ Wk,
            const float* __restrict__ Wv)
{
    const int w = blockIdx.z >> 3;
    const int b = blockIdx.z & 7;
    const int h = blockIdx.y;
    const int row0 = blockIdx.x * BM;

    const float* W   = (w == 0) ? Wq : (w == 1) ? Wk : Wv;
    float*       out = (w == 0) ? g_q : (w == 1) ? g_k : g_v;

    const float* A  = x + (size_t)b * Dd * Ls;
    const float* Bm = W + (size_t)h * Dd * DK;
    float*       C  = out + (size_t)(b * NH + h) * Ls * DK;

    float acc[4][4][4] = {};
    gemm_main<1, 0>(A, Ls, Bm, DK, Dd, row0, 0, nullptr, acc);

    const int lane = threadIdx.x & 31, wid = threadIdx.x >> 5;
    const int wm = wid & 1, wn = wid >> 1;
    const int r = lane >> 2, c2 = (lane & 3) << 1;
    #pragma unroll
    for (int mt = 0; mt < 4; mt++)
        #pragma unroll
        for (int nt = 0; nt < 4; nt++) {
            int m0 = row0 + wm * 64 + mt * 16 + r;
            int n  = wn * 32 + nt * 8 + c2;
            *(float2*)&C[(size_t)m0 * DK + n]       = make_float2(acc[mt][nt][0], acc[mt][nt][1]);
            *(float2*)&C[(size_t)(m0 + 8) * DK + n] = make_float2(acc[mt][nt][2], acc[mt][nt][3]);
        }
}

// scores: E[bh,q,k] = exp(scale*QK^T + (1-mask[q])*NEG); atomic col sums -> g_ci
__global__ void __launch_bounds__(256, 2)
scores_kernel(const float* __restrict__ mask)
{
    const int bh = blockIdx.z;
    const int b  = bh >> 3;
    const int row0 = blockIdx.y * BM;
    const int col0 = blockIdx.x * BN;

    const float* A  = g_q + (size_t)bh * Ls * DK;
    const float* Bm = g_k + (size_t)bh * Ls * DK;
    float*       C  = g_s + (size_t)bh * Ls * Ls;
    float*    gsum  = g_ci + (size_t)bh * Ls;

    float acc[4][4][4] = {};
    gemm_main<0, 1>(A, DK, Bm, DK, DK, row0, col0, nullptr, acc);

    const float scale = 0.088388347648318447f;  // 1/sqrt(128)
    const int lane = threadIdx.x & 31, wid = threadIdx.x >> 5;
    const int wm = wid & 1, wn = wid >> 1;
    const int r = lane >> 2, c2 = (lane & 3) << 1;

    float cs[4][2] = {};
    #pragma unroll
    for (int mt = 0; mt < 4; mt++) {
        int m0 = row0 + wm * 64 + mt * 16 + r;
        float md0 = (1.0f - __ldg(&mask[(size_t)b * Ls + m0]))     * NEGV;
        float md1 = (1.0f - __ldg(&mask[(size_t)b * Ls + m0 + 8])) * NEGV;
        #pragma unroll
        for (int nt = 0; nt < 4; nt++) {
            int n = col0 + wn * 32 + nt * 8 + c2;
            float e0 = __expf(acc[mt][nt][0] * scale + md0);
            float e1 = __expf(acc[mt][nt][1] * scale + md0);
            float e2 = __expf(acc[mt][nt][2] * scale + md1);
            float e3 = __expf(acc[mt][nt][3] * scale + md1);
            *(float2*)&C[(size_t)m0 * Ls + n]       = make_float2(e0, e1);
            *(float2*)&C[(size_t)(m0 + 8) * Ls + n] = make_float2(e2, e3);
            cs[nt][0] += e0 + e2;
            cs[nt][1] += e1 + e3;
        }
    }
    #pragma unroll
    for (int nt = 0; nt < 4; nt++) {
        int n = col0 + wn * 32 + nt * 8 + c2;
        atomicAdd(&gsum[n],     cs[nt][0]);
        atomicAdd(&gsum[n + 1], cs[nt][1]);
    }
}

// invert column sums in place
__global__ void inv_kernel()
{
    int i = blockIdx.x * 256 + threadIdx.x;
    g_ci[i] = 1.0f / g_ci[i];
}

// heads: hd[b,l,h*128+dv] = sum_k E[q,k] * (v[k,dv]*inv[k])
__global__ void __launch_bounds__(256, 2)
heads_kernel()
{
    const int bh = blockIdx.y;
    const int b  = bh >> 3;
    const int h  = bh & 7;
    const int row0 = blockIdx.x * BM;

    const float* A  = g_s + (size_t)bh * Ls * Ls;
    const float* Bm = g_v + (size_t)bh * Ls * DK;
    const float* gi = g_ci + (size_t)bh * Ls;
    float*       C  = g_hd + (size_t)b * Ls * (NH * DK) + h * DK;

    float acc[4][4][4] = {};
    gemm_main<0, 2>(A, Ls, Bm, DK, Ls, row0, 0, gi, acc);

    const int lane = threadIdx.x & 31, wid = threadIdx.x >> 5;
    const int wm = wid & 1, wn = wid >> 1;
    const int r = lane >> 2, c2 = (lane & 3) << 1;
    #pragma unroll
    for (int mt = 0; mt < 4; mt++)
        #pragma unroll
        for (int nt = 0; nt < 4; nt++) {
            int m0 = row0 + wm * 64 + mt * 16 + r;
            int n  = wn * 32 + nt * 8 + c2;
            *(float2*)&C[(size_t)m0 * (NH * DK) + n]       = make_float2(acc[mt][nt][0], acc[mt][nt][1]);
            *(float2*)&C[(size_t)(m0 + 8) * (NH * DK) + n] = make_float2(acc[mt][nt][2], acc[mt][nt][3]);
        }
}

// out: out[b, n, m] = sum_j hd[b,m,j] * Wo[j,n]  (transposed write, fused)
__global__ void __launch_bounds__(256, 2)
out_kernel(const float* __restrict__ Wo, float* __restrict__ outp)
{
    const int b = blockIdx.z;
    const int row0 = blockIdx.y * BM;
    const int col0 = blockIdx.x * BN;

    const float* A = g_hd + (size_t)b * Ls * Dd;
    float*       C = outp + (size_t)b * Dd * Ls;   // [D][L]

    float acc[4][4][4] = {};
    gemm_main<0, 0>(A, Dd, Wo, Dd, Dd, row0, col0, nullptr, acc);

    const int lane = threadIdx.x & 31, wid = threadIdx.x >> 5;
    const int wm = wid & 1, wn = wid >> 1;
    const int r = lane >> 2, c2 = (lane & 3) << 1;
    #pragma unroll
    for (int mt = 0; mt < 4; mt++) {
        int m0 = row0 + wm * 64 + mt * 16 + r;
        #pragma unroll
        for (int nt = 0; nt < 4; nt++) {
            int n = col0 + wn * 32 + nt * 8 + c2;
            C[(size_t)n * Ls + m0]           = acc[mt][nt][0];
            C[(size_t)(n + 1) * Ls + m0]     = acc[mt][nt][1];
            C[(size_t)n * Ls + m0 + 8]       = acc[mt][nt][2];
            C[(size_t)(n + 1) * Ls + m0 + 8] = acc[mt][nt][3];
        }
    }
}

// -------------------- launch --------------------
extern "C" void kernel_launch(void* const* d_in, const int* in_sizes, int n_in,
                              void* d_out, int out_size)
{
    const float* x    = (const float*)d_in[0];   // [B, D, L]
    const float* mask = (const float*)d_in[1];   // [B, L]
    const float* Wq   = (const float*)d_in[2];   // [H, D, DK]
    const float* Wk   = (const float*)d_in[3];
    const float* Wv   = (const float*)d_in[4];
    const float* Wo   = (const float*)d_in[5];   // [D, H*DK]
    float* out = (float*)d_out;                  // [B, D, L]

    float* ci_ptr; cudaGetSymbolAddress((void**)&ci_ptr, g_ci);
    cudaMemsetAsync(ci_ptr, 0, (size_t)Bsz * NH * Ls * sizeof(float), 0);

    {   // QKV projections (x read transposed in-kernel)
        dim3 g(Ls / BM, NH, 3 * Bsz);
        proj_kernel<<<g, 256>>>(x, Wq, Wk, Wv);
    }
    {   // scores -> E = exp(...), atomic column sums
        dim3 g(Ls / BN, Ls / BM, Bsz * NH);
        scores_kernel<<<g, 256>>>(mask);
    }
    {   // invert column sums
        inv_kernel<<<(Bsz * NH * Ls) / 256, 256>>>();
    }
    {   // heads = E @ (V * inv)
        dim3 g(Ls / BM, Bsz * NH);
        heads_kernel<<<g, 256>>>();
    }
    {   // output projection with fused transpose
        dim3 g(Dd / BN, Ls / BM, Bsz);
        out_kernel<<<g, 256>>>(Wo, out);
    }
}

// round 7
// speedup vs baseline: 1.0150x; 1.0150x over previous
#include <cuda_runtime.h>
#include <cuda_bf16.h>
#include <cstdint>

#define Bsz 8
#define Dd  1024
#define Ls  1024
#define NH  8
#define DK  128
#define NEGV (-1e30f)

// -------------------- scratch (device globals; no allocation) --------------------
__device__ float g_q  [(size_t)Bsz * NH * Ls * DK];        // [B,H,L,DK]  32MB
__device__ float g_k  [(size_t)Bsz * NH * Ls * DK];        // 32MB
__device__ float g_v  [(size_t)Bsz * NH * Ls * DK];        // 32MB
__device__ float g_s  [(size_t)Bsz * NH * Ls * Ls];        // E = exp(S)  256MB
__device__ float g_ci [(size_t)Bsz * NH * Ls];             // col sums -> 1/sum
__device__ float g_hd [(size_t)Bsz * Ls * (NH * DK)];      // [B,L,H*DK]  32MB

// ==================== tf32 mma GEMM: 128x128 tile, BK=16, 256 threads ====================
// k-pair smem layout: T[k2][col] = (val at k=2*k2, val at k=2*k2+1) as uint2 (tf32 bits).
// Row stride 132 float2 => (132 mod 16)==4 => fragment LDS.64 conflict-free.
#define BM 128
#define BN 128
#define BK 16
#define LDT2 132

__device__ __forceinline__ uint32_t f2tf(float f) {
    uint32_t u;
    asm("cvt.rna.tf32.f32 %0, %1;" : "=r"(u) : "f"(f));
    return u;
}

__device__ __forceinline__ void mma_tf32(float c[4], const uint32_t a[4], const uint32_t b[2]) {
    asm volatile(
        "mma.sync.aligned.m16n8k8.row.col.f32.tf32.tf32.f32 "
        "{%0,%1,%2,%3}, {%4,%5,%6,%7}, {%8,%9}, {%0,%1,%2,%3};"
        : "+f"(c[0]), "+f"(c[1]), "+f"(c[2]), "+f"(c[3])
        : "r"(a[0]), "r"(a[1]), "r"(a[2]), "r"(a[3]), "r"(b[0]), "r"(b[1]));
}

// AMODE: 0 = A row-major [M][lda]; 1 = A stored [K][ldm] (contract rows)
// BMODE: 0 = B row-major [K][ldb]; 1 = B stored [N][ldn]; 2 = mode 0 scaled by gi[k]

// ---- global loads into prefetch registers ----
// Mode "along-k" (AMODE0 / BMODE1): float4 of 4 consecutive k for one row.
// Mode "k-pair"  (AMODE1 / BMODE0/2): two float2 from adjacent k-rows, packed
//   ra = {even.x, even.y, odd.x, odd.y}.

template <int AMODE>
__device__ __forceinline__ void ldgA(float4 r[2], const float* __restrict__ A,
                                     int lda, int row0, int k0)
{
    const int t = threadIdx.x;
    #pragma unroll
    for (int it = 0; it < 2; it++) {
        int idx = t + it * 256;
        if (AMODE == 1) {
            int k2 = idx >> 6, m2 = (idx & 63) << 1;
            const float* p = &A[(size_t)(k0 + (k2 << 1)) * lda + row0 + m2];
            float2 e = *(const float2*)p;
            float2 o = *(const float2*)(p + lda);
            r[it] = make_float4(e.x, e.y, o.x, o.y);
        } else {
            int m = idx >> 2, c4 = (idx & 3) << 2;
            r[it] = *(const float4*)&A[(size_t)(row0 + m) * lda + k0 + c4];
        }
    }
}

template <int AMODE>
__device__ __forceinline__ void stsA(uint2 (*As)[LDT2], const float4 r[2])
{
    const int t = threadIdx.x;
    #pragma unroll
    for (int it = 0; it < 2; it++) {
        int idx = t + it * 256;
        if (AMODE == 1) {
            int k2 = idx >> 6, m2 = (idx & 63) << 1;
            // As[k2][m2] = (even, odd) ; As[k2][m2+1] = (even, odd)
            uint4 u = { f2tf(r[it].x), f2tf(r[it].z), f2tf(r[it].y), f2tf(r[it].w) };
            *(uint4*)&As[k2][m2] = u;
        } else {
            int m = idx >> 2, c4 = (idx & 3) << 2;
            uint2 u0 = { f2tf(r[it].x), f2tf(r[it].y) };
            uint2 u1 = { f2tf(r[it].z), f2tf(r[it].w) };
            As[(c4 >> 1)][m]     = u0;
            As[(c4 >> 1) + 1][m] = u1;
        }
    }
}

template <int BMODE>
__device__ __forceinline__ void ldgB(float4 r[2], float2 s[2], const float* __restrict__ B,
                                     int ldb, int col0, int k0, const float* __restrict__ gi)
{
    const int t = threadIdx.x;
    #pragma unroll
    for (int it = 0; it < 2; it++) {
        int idx = t + it * 256;
        if (BMODE == 1) {
            int n = idx >> 2, c4 = (idx & 3) << 2;
            r[it] = *(const float4*)&B[(size_t)(col0 + n) * ldb + k0 + c4];
        } else {
            int k2 = idx >> 6, n2 = (idx & 63) << 1;
            const float* p = &B[(size_t)(k0 + (k2 << 1)) * ldb + col0 + n2];
            float2 e = *(const float2*)p;
            float2 o = *(const float2*)(p + ldb);
            r[it] = make_float4(e.x, e.y, o.x, o.y);
            if (BMODE == 2) {
                s[it].x = __ldg(&gi[k0 + (k2 << 1)]);
                s[it].y = __ldg(&gi[k0 + (k2 << 1) + 1]);
            }
        }
    }
}

template <int BMODE>
__device__ __forceinline__ void stsB(uint2 (*Bs)[LDT2], const float4 r[2], const float2 s[2])
{
    const int t = threadIdx.x;
    #pragma unroll
    for (int it = 0; it < 2; it++) {
        int idx = t + it * 256;
        if (BMODE == 1) {
            int n = idx >> 2, c4 = (idx & 3) << 2;
            uint2 u0 = { f2tf(r[it].x), f2tf(r[it].y) };
            uint2 u1 = { f2tf(r[it].z), f2tf(r[it].w) };
            Bs[(c4 >> 1)][n]     = u0;
            Bs[(c4 >> 1) + 1][n] = u1;
        } else {
            int k2 = idx >> 6, n2 = (idx & 63) << 1;
            float4 v = r[it];
            if (BMODE == 2) { v.x *= s[it].x; v.y *= s[it].x; v.z *= s[it].y; v.w *= s[it].y; }
            uint4 u = { f2tf(v.x), f2tf(v.z), f2tf(v.y), f2tf(v.w) };
            *(uint4*)&Bs[k2][n2] = u;
        }
    }
}

// Double-buffered mainloop. Warp tile 64x32 (2x4 warp grid), acc[4][4][4].
template <int AMODE, int BMODE>
__device__ __forceinline__ void gemm_main(
    const float* __restrict__ A, int lda,
    const float* __restrict__ B, int ldb,
    int Kdim, int row0, int col0,
    const float* __restrict__ gi,
    float acc[4][4][4])
{
    __shared__ uint2 As[2][BK / 2][LDT2];
    __shared__ uint2 Bs[2][BK / 2][LDT2];

    const int lane = threadIdx.x & 31;
    const int wid  = threadIdx.x >> 5;
    const int wm   = wid & 1;
    const int wn   = wid >> 1;
    const int r    = lane >> 2;
    const int q4   = lane & 3;          // k-pair row selector within a k8 step

    float4 ra[2], rb[2];
    float2 rs[2];

    ldgA<AMODE>(ra, A, lda, row0, 0);
    ldgB<BMODE>(rb, rs, B, ldb, col0, 0, gi);
    stsA<AMODE>(As[0], ra);
    stsB<BMODE>(Bs[0], rb, rs);
    __syncthreads();

    const int nk = Kdim / BK;
    for (int i = 0; i < nk; i++) {
        const int cur = i & 1;
        if (i + 1 < nk) {
            ldgA<AMODE>(ra, A, lda, row0, (i + 1) * BK);
            ldgB<BMODE>(rb, rs, B, ldb, col0, (i + 1) * BK, gi);
        }

        #pragma unroll
        for (int ks = 0; ks < 2; ks++) {
            const int kb2 = ks * 4 + q4;
            uint32_t af[4][4], bf[4][2];
            #pragma unroll
            for (int mt = 0; mt < 4; mt++) {
                int ms = wm * 64 + mt * 16 + r;
                uint2 lo = As[cur][kb2][ms];
                uint2 hi = As[cur][kb2][ms + 8];
                af[mt][0] = lo.x; af[mt][1] = hi.x;
                af[mt][2] = lo.y; af[mt][3] = hi.y;
            }
            #pragma unroll
            for (int nt = 0; nt < 4; nt++) {
                int ns = wn * 32 + nt * 8 + r;
                uint2 bb = Bs[cur][kb2][ns];
                bf[nt][0] = bb.x; bf[nt][1] = bb.y;
            }
            #pragma unroll
            for (int mt = 0; mt < 4; mt++)
                #pragma unroll
                for (int nt = 0; nt < 4; nt++)
                    mma_tf32(acc[mt][nt], af[mt], bf[nt]);
        }

        if (i + 1 < nk) {
            stsA<AMODE>(As[cur ^ 1], ra);
            stsB<BMODE>(Bs[cur ^ 1], rb, rs);
            __syncthreads();
        }
    }
}

// ==================== kernels ====================

// proj: q/k/v[b,h,l,dk] = sum_d x[b,d,l] * W[h,d,dk]
__global__ void __launch_bounds__(256, 2)
proj_kernel(const float* __restrict__ x,
            const float* __restrict__ Wq, const float* __restrict__ Wk,
            const float* __restrict__ Wv)
{
    const int w = blockIdx.z >> 3;
    const int b = blockIdx.z & 7;
    const int h = blockIdx.y;
    const int row0 = blockIdx.x * BM;

    const float* W   = (w == 0) ? Wq : (w == 1) ? Wk : Wv;
    float*       out = (w == 0) ? g_q : (w == 1) ? g_k : g_v;

    const float* A  = x + (size_t)b * Dd * Ls;
    const float* Bm = W + (size_t)h * Dd * DK;
    float*       C  = out + (size_t)(b * NH + h) * Ls * DK;

    float acc[4][4][4] = {};
    gemm_main<1, 0>(A, Ls, Bm, DK, Dd, row0, 0, nullptr, acc);

    const int lane = threadIdx.x & 31, wid = threadIdx.x >> 5;
    const int wm = wid & 1, wn = wid >> 1;
    const int r = lane >> 2, c2 = (lane & 3) << 1;
    #pragma unroll
    for (int mt = 0; mt < 4; mt++)
        #pragma unroll
        for (int nt = 0; nt < 4; nt++) {
            int m0 = row0 + wm * 64 + mt * 16 + r;
            int n  = wn * 32 + nt * 8 + c2;
            *(float2*)&C[(size_t)m0 * DK + n]       = make_float2(acc[mt][nt][0], acc[mt][nt][1]);
            *(float2*)&C[(size_t)(m0 + 8) * DK + n] = make_float2(acc[mt][nt][2], acc[mt][nt][3]);
        }
}

// scores: E[bh,q,k] = exp(scale*QK^T + (1-mask[q])*NEG); atomic col sums -> g_ci
__global__ void __launch_bounds__(256, 2)
scores_kernel(const float* __restrict__ mask)
{
    const int bh = blockIdx.z;
    const int b  = bh >> 3;
    const int row0 = blockIdx.y * BM;
    const int col0 = blockIdx.x * BN;

    const float* A  = g_q + (size_t)bh * Ls * DK;
    const float* Bm = g_k + (size_t)bh * Ls * DK;
    float*       C  = g_s + (size_t)bh * Ls * Ls;
    float*    gsum  = g_ci + (size_t)bh * Ls;

    float acc[4][4][4] = {};
    gemm_main<0, 1>(A, DK, Bm, DK, DK, row0, col0, nullptr, acc);

    const float scale = 0.088388347648318447f;  // 1/sqrt(128)
    const int lane = threadIdx.x & 31, wid = threadIdx.x >> 5;
    const int wm = wid & 1, wn = wid >> 1;
    const int r = lane >> 2, c2 = (lane & 3) << 1;

    float cs[4][2] = {};
    #pragma unroll
    for (int mt = 0; mt < 4; mt++) {
        int m0 = row0 + wm * 64 + mt * 16 + r;
        float md0 = (1.0f - __ldg(&mask[(size_t)b * Ls + m0]))     * NEGV;
        float md1 = (1.0f - __ldg(&mask[(size_t)b * Ls + m0 + 8])) * NEGV;
        #pragma unroll
        for (int nt = 0; nt < 4; nt++) {
            int n = col0 + wn * 32 + nt * 8 + c2;
            float e0 = __expf(acc[mt][nt][0] * scale + md0);
            float e1 = __expf(acc[mt][nt][1] * scale + md0);
            float e2 = __expf(acc[mt][nt][2] * scale + md1);
            float e3 = __expf(acc[mt][nt][3] * scale + md1);
            *(float2*)&C[(size_t)m0 * Ls + n]       = make_float2(e0, e1);
            *(float2*)&C[(size_t)(m0 + 8) * Ls + n] = make_float2(e2, e3);
            cs[nt][0] += e0 + e2;
            cs[nt][1] += e1 + e3;
        }
    }
    #pragma unroll
    for (int nt = 0; nt < 4; nt++) {
        int n = col0 + wn * 32 + nt * 8 + c2;
        atomicAdd(&gsum[n],     cs[nt][0]);
        atomicAdd(&gsum[n + 1], cs[nt][1]);
    }
}

// invert column sums in place
__global__ void inv_kernel()
{
    int i = blockIdx.x * 256 + threadIdx.x;
    g_ci[i] = 1.0f / g_ci[i];
}

// heads: hd[b,l,h*128+dv] = sum_k E[q,k] * (v[k,dv]*inv[k])
__global__ void __launch_bounds__(256, 2)
heads_kernel()
{
    const int bh = blockIdx.y;
    const int b  = bh >> 3;
    const int h  = bh & 7;
    const int row0 = blockIdx.x * BM;

    const float* A  = g_s + (size_t)bh * Ls * Ls;
    const float* Bm = g_v + (size_t)bh * Ls * DK;
    const float* gi = g_ci + (size_t)bh * Ls;
    float*       C  = g_hd + (size_t)b * Ls * (NH * DK) + h * DK;

    float acc[4][4][4] = {};
    gemm_main<0, 2>(A, Ls, Bm, DK, Ls, row0, 0, gi, acc);

    const int lane = threadIdx.x & 31, wid = threadIdx.x >> 5;
    const int wm = wid & 1, wn = wid >> 1;
    const int r = lane >> 2, c2 = (lane & 3) << 1;
    #pragma unroll
    for (int mt = 0; mt < 4; mt++)
        #pragma unroll
        for (int nt = 0; nt < 4; nt++) {
            int m0 = row0 + wm * 64 + mt * 16 + r;
            int n  = wn * 32 + nt * 8 + c2;
            *(float2*)&C[(size_t)m0 * (NH * DK) + n]       = make_float2(acc[mt][nt][0], acc[mt][nt][1]);
            *(float2*)&C[(size_t)(m0 + 8) * (NH * DK) + n] = make_float2(acc[mt][nt][2], acc[mt][nt][3]);
        }
}

// out: out[b, n, m] = sum_j hd[b,m,j] * Wo[j,n]  (transposed write, fused)
__global__ void __launch_bounds__(256, 2)
out_kernel(const float* __restrict__ Wo, float* __restrict__ outp)
{
    const int b = blockIdx.z;
    const int row0 = blockIdx.y * BM;
    const int col0 = blockIdx.x * BN;

    const float* A = g_hd + (size_t)b * Ls * Dd;
    float*       C = outp + (size_t)b * Dd * Ls;   // [D][L]

    float acc[4][4][4] = {};
    gemm_main<0, 0>(A, Dd, Wo, Dd, Dd, row0, col0, nullptr, acc);

    const int lane = threadIdx.x & 31, wid = threadIdx.x >> 5;
    const int wm = wid & 1, wn = wid >> 1;
    const int r = lane >> 2, c2 = (lane & 3) << 1;
    #pragma unroll
    for (int mt = 0; mt < 4; mt++) {
        int m0 = row0 + wm * 64 + mt * 16 + r;
        #pragma unroll
        for (int nt = 0; nt < 4; nt++) {
            int n = col0 + wn * 32 + nt * 8 + c2;
            C[(size_t)n * Ls + m0]           = acc[mt][nt][0];
            C[(size_t)(n + 1) * Ls + m0]     = acc[mt][nt][1];
            C[(size_t)n * Ls + m0 + 8]       = acc[mt][nt][2];
            C[(size_t)(n + 1) * Ls + m0 + 8] = acc[mt][nt][3];
        }
    }
}

// -------------------- launch --------------------
extern "C" void kernel_launch(void* const* d_in, const int* in_sizes, int n_in,
                              void* d_out, int out_size)
{
    const float* x    = (const float*)d_in[0];   // [B, D, L]
    const float* mask = (const float*)d_in[1];   // [B, L]
    const float* Wq   = (const float*)d_in[2];   // [H, D, DK]
    const float* Wk   = (const float*)d_in[3];
    const float* Wv   = (const float*)d_in[4];
    const float* Wo   = (const float*)d_in[5];   // [D, H*DK]
    float* out = (float*)d_out;                  // [B, D, L]

    float* ci_ptr; cudaGetSymbolAddress((void**)&ci_ptr, g_ci);
    cudaMemsetAsync(ci_ptr, 0, (size_t)Bsz * NH * Ls * sizeof(float), 0);

    {   // QKV projections (x read transposed in-kernel)
        dim3 g(Ls / BM, NH, 3 * Bsz);
        proj_kernel<<<g, 256>>>(x, Wq, Wk, Wv);
    }
    {   // scores -> E = exp(...), atomic column sums
        dim3 g(Ls / BN, Ls / BM, Bsz * NH);
        scores_kernel<<<g, 256>>>(mask);
    }
    {   // invert column sums
        inv_kernel<<<(Bsz * NH * Ls) / 256, 256>>>();
    }
    {   // heads = E @ (V * inv)
        dim3 g(Ls / BM, Bsz * NH);
        heads_kernel<<<g, 256>>>();
    }
    {   // output projection with fused transpose
        dim3 g(Dd / BN, Ls / BM, Bsz);
        out_kernel<<<g, 256>>>(Wo, out);
    }
}

// round 17
// speedup vs baseline: 1.0636x; 1.0479x over previous
#include <cuda_runtime.h>
#include <cuda_bf16.h>
#include <cstdint>

#define Bsz 8
#define Dd  1024
#define Ls  1024
#define NH  8
#define DK  128
#define NEGV (-1e30f)

// -------------------- scratch (device globals; no allocation) --------------------
__device__ float g_q  [(size_t)Bsz * NH * Ls * DK];        // [B,H,L,DK]  32MB
__device__ float g_k  [(size_t)Bsz * NH * Ls * DK];        // 32MB
__device__ float g_v  [(size_t)Bsz * NH * Ls * DK];        // 32MB
__device__ float g_s  [(size_t)Bsz * NH * Ls * Ls];        // E = exp(S)  256MB
__device__ float g_ci [(size_t)Bsz * NH * Ls];             // col sums -> 1/sum
__device__ float g_hd [(size_t)Bsz * Ls * (NH * DK)];      // [B,L,H*DK]  32MB

// ==================== tf32 mma GEMM: 128x128 tile, BK=16, 128 threads ====================
// 4 warps, warp tile 64x64 (2x2 warp grid) -> 128B of fragment LDS per MMA.
// k-pair smem layout: T[k2][col] = (val at k=2*k2, val at k=2*k2+1) as uint2 (tf32 bits).
// Row stride 132 uint2 => fragment LDS.64 conflict-free.
#define BM 128
#define BN 128
#define BK 16
#define LDT2 132
#define NTHD 128

__device__ __forceinline__ uint32_t f2tf(float f) {
    uint32_t u;
    asm("cvt.rna.tf32.f32 %0, %1;" : "=r"(u) : "f"(f));
    return u;
}

__device__ __forceinline__ void mma_tf32(float c[4], const uint32_t a[4], const uint32_t b[2]) {
    asm volatile(
        "mma.sync.aligned.m16n8k8.row.col.f32.tf32.tf32.f32 "
        "{%0,%1,%2,%3}, {%4,%5,%6,%7}, {%8,%9}, {%0,%1,%2,%3};"
        : "+f"(c[0]), "+f"(c[1]), "+f"(c[2]), "+f"(c[3])
        : "r"(a[0]), "r"(a[1]), "r"(a[2]), "r"(a[3]), "r"(b[0]), "r"(b[1]));
}

// AMODE: 0 = A row-major [M][lda]; 1 = A stored [K][ldm] (contract rows)
// BMODE: 0 = B row-major [K][ldb]; 1 = B stored [N][ldn]; 2 = mode 0 scaled by gi[k]

template <int AMODE>
__device__ __forceinline__ void ldgA(float4 r[4], const float* __restrict__ A,
                                     int lda, int row0, int k0)
{
    const int t = threadIdx.x;
    #pragma unroll
    for (int it = 0; it < 4; it++) {
        int idx = t + it * NTHD;
        if (AMODE == 1) {
            int k2 = idx >> 6, m2 = (idx & 63) << 1;
            const float* p = &A[(size_t)(k0 + (k2 << 1)) * lda + row0 + m2];
            float2 e = *(const float2*)p;
            float2 o = *(const float2*)(p + lda);
            r[it] = make_float4(e.x, e.y, o.x, o.y);
        } else {
            int m = idx >> 2, c4 = (idx & 3) << 2;
            r[it] = *(const float4*)&A[(size_t)(row0 + m) * lda + k0 + c4];
        }
    }
}

template <int AMODE>
__device__ __forceinline__ void stsA(uint2 (*As)[LDT2], const float4 r[4])
{
    const int t = threadIdx.x;
    #pragma unroll
    for (int it = 0; it < 4; it++) {
        int idx = t + it * NTHD;
        if (AMODE == 1) {
            int k2 = idx >> 6, m2 = (idx & 63) << 1;
            uint4 u = { f2tf(r[it].x), f2tf(r[it].z), f2tf(r[it].y), f2tf(r[it].w) };
            *(uint4*)&As[k2][m2] = u;
        } else {
            int m = idx >> 2, c4 = (idx & 3) << 2;
            uint2 u0 = { f2tf(r[it].x), f2tf(r[it].y) };
            uint2 u1 = { f2tf(r[it].z), f2tf(r[it].w) };
            As[(c4 >> 1)][m]     = u0;
            As[(c4 >> 1) + 1][m] = u1;
        }
    }
}

template <int BMODE>
__device__ __forceinline__ void ldgB(float4 r[4], float2 s[4], const float* __restrict__ B,
                                     int ldb, int col0, int k0, const float* __restrict__ gi)
{
    const int t = threadIdx.x;
    #pragma unroll
    for (int it = 0; it < 4; it++) {
        int idx = t + it * NTHD;
        if (BMODE == 1) {
            int n = idx >> 2, c4 = (idx & 3) << 2;
            r[it] = *(const float4*)&B[(size_t)(col0 + n) * ldb + k0 + c4];
        } else {
            int k2 = idx >> 6, n2 = (idx & 63) << 1;
            const float* p = &B[(size_t)(k0 + (k2 << 1)) * ldb + col0 + n2];
            float2 e = *(const float2*)p;
            float2 o = *(const float2*)(p + ldb);
            r[it] = make_float4(e.x, e.y, o.x, o.y);
            if (BMODE == 2) {
                s[it].x = __ldg(&gi[k0 + (k2 << 1)]);
                s[it].y = __ldg(&gi[k0 + (k2 << 1) + 1]);
            }
        }
    }
}

template <int BMODE>
__device__ __forceinline__ void stsB(uint2 (*Bs)[LDT2], const float4 r[4], const float2 s[4])
{
    const int t = threadIdx.x;
    #pragma unroll
    for (int it = 0; it < 4; it++) {
        int idx = t + it * NTHD;
        if (BMODE == 1) {
            int n = idx >> 2, c4 = (idx & 3) << 2;
            uint2 u0 = { f2tf(r[it].x), f2tf(r[it].y) };
            uint2 u1 = { f2tf(r[it].z), f2tf(r[it].w) };
            Bs[(c4 >> 1)][n]     = u0;
            Bs[(c4 >> 1) + 1][n] = u1;
        } else {
            int k2 = idx >> 6, n2 = (idx & 63) << 1;
            float4 v = r[it];
            if (BMODE == 2) { v.x *= s[it].x; v.y *= s[it].x; v.z *= s[it].y; v.w *= s[it].y; }
            uint4 u = { f2tf(v.x), f2tf(v.z), f2tf(v.y), f2tf(v.w) };
            *(uint4*)&Bs[k2][n2] = u;
        }
    }
}

// Double-buffered mainloop. Warp tile 64x64 (2x2 warp grid), acc[4][8][4].
template <int AMODE, int BMODE>
__device__ __forceinline__ void gemm_main(
    const float* __restrict__ A, int lda,
    const float* __restrict__ B, int ldb,
    int Kdim, int row0, int col0,
    const float* __restrict__ gi,
    float acc[4][8][4])
{
    __shared__ uint2 As[2][BK / 2][LDT2];
    __shared__ uint2 Bs[2][BK / 2][LDT2];

    const int lane = threadIdx.x & 31;
    const int wid  = threadIdx.x >> 5;
    const int wm   = wid & 1;
    const int wn   = wid >> 1;
    const int r    = lane >> 2;
    const int q4   = lane & 3;

    float4 ra[4], rb[4];
    float2 rs[4];

    ldgA<AMODE>(ra, A, lda, row0, 0);
    ldgB<BMODE>(rb, rs, B, ldb, col0, 0, gi);
    stsA<AMODE>(As[0], ra);
    stsB<BMODE>(Bs[0], rb, rs);
    __syncthreads();

    const int nk = Kdim / BK;
    for (int i = 0; i < nk; i++) {
        const int cur = i & 1;
        if (i + 1 < nk) {
            ldgA<AMODE>(ra, A, lda, row0, (i + 1) * BK);
            ldgB<BMODE>(rb, rs, B, ldb, col0, (i + 1) * BK, gi);
        }

        #pragma unroll
        for (int ks = 0; ks < 2; ks++) {
            const int kb2 = ks * 4 + q4;
            uint32_t af[4][4], bf[8][2];
            #pragma unroll
            for (int mt = 0; mt < 4; mt++) {
                int ms = wm * 64 + mt * 16 + r;
                uint2 lo = As[cur][kb2][ms];
                uint2 hi = As[cur][kb2][ms + 8];
                af[mt][0] = lo.x; af[mt][1] = hi.x;
                af[mt][2] = lo.y; af[mt][3] = hi.y;
            }
            #pragma unroll
            for (int nt = 0; nt < 8; nt++) {
                int ns = wn * 64 + nt * 8 + r;
                uint2 bb = Bs[cur][kb2][ns];
                bf[nt][0] = bb.x; bf[nt][1] = bb.y;
            }
            #pragma unroll
            for (int mt = 0; mt < 4; mt++)
                #pragma unroll
                for (int nt = 0; nt < 8; nt++)
                    mma_tf32(acc[mt][nt], af[mt], bf[nt]);
        }

        if (i + 1 < nk) {
            stsA<AMODE>(As[cur ^ 1], ra);
            stsB<BMODE>(Bs[cur ^ 1], rb, rs);
            __syncthreads();
        }
    }
}

// ==================== kernels ====================

// proj: q/k/v[b,h,l,dk] = sum_d x[b,d,l] * W[h,d,dk]
__global__ void __launch_bounds__(NTHD, 2)
proj_kernel(const float* __restrict__ x,
            const float* __restrict__ Wq, const float* __restrict__ Wk,
            const float* __restrict__ Wv)
{
    const int w = blockIdx.z >> 3;
    const int b = blockIdx.z & 7;
    const int h = blockIdx.y;
    const int row0 = blockIdx.x * BM;

    const float* W   = (w == 0) ? Wq : (w == 1) ? Wk : Wv;
    float*       out = (w == 0) ? g_q : (w == 1) ? g_k : g_v;

    const float* A  = x + (size_t)b * Dd * Ls;
    const float* Bm = W + (size_t)h * Dd * DK;
    float*       C  = out + (size_t)(b * NH + h) * Ls * DK;

    float acc[4][8][4] = {};
    gemm_main<1, 0>(A, Ls, Bm, DK, Dd, row0, 0, nullptr, acc);

    const int lane = threadIdx.x & 31, wid = threadIdx.x >> 5;
    const int wm = wid & 1, wn = wid >> 1;
    const int r = lane >> 2, c2 = (lane & 3) << 1;
    #pragma unroll
    for (int mt = 0; mt < 4; mt++)
        #pragma unroll
        for (int nt = 0; nt < 8; nt++) {
            int m0 = row0 + wm * 64 + mt * 16 + r;
            int n  = wn * 64 + nt * 8 + c2;
            *(float2*)&C[(size_t)m0 * DK + n]       = make_float2(acc[mt][nt][0], acc[mt][nt][1]);
            *(float2*)&C[(size_t)(m0 + 8) * DK + n] = make_float2(acc[mt][nt][2], acc[mt][nt][3]);
        }
}

// scores: E[bh,q,k] = exp(scale*QK^T + (1-mask[q])*NEG); atomic col sums -> g_ci
__global__ void __launch_bounds__(NTHD, 2)
scores_kernel(const float* __restrict__ mask)
{
    const int bh = blockIdx.z;
    const int b  = bh >> 3;
    const int row0 = blockIdx.y * BM;
    const int col0 = blockIdx.x * BN;

    const float* A  = g_q + (size_t)bh * Ls * DK;
    const float* Bm = g_k + (size_t)bh * Ls * DK;
    float*       C  = g_s + (size_t)bh * Ls * Ls;
    float*    gsum  = g_ci + (size_t)bh * Ls;

    float acc[4][8][4] = {};
    gemm_main<0, 1>(A, DK, Bm, DK, DK, row0, col0, nullptr, acc);

    const float scale = 0.088388347648318447f;  // 1/sqrt(128)
    const int lane = threadIdx.x & 31, wid = threadIdx.x >> 5;
    const int wm = wid & 1, wn = wid >> 1;
    const int r = lane >> 2, c2 = (lane & 3) << 1;

    float cs[8][2] = {};
    #pragma unroll
    for (int mt = 0; mt < 4; mt++) {
        int m0 = row0 + wm * 64 + mt * 16 + r;
        float md0 = (1.0f - __ldg(&mask[(size_t)b * Ls + m0]))     * NEGV;
        float md1 = (1.0f - __ldg(&mask[(size_t)b * Ls + m0 + 8])) * NEGV;
        #pragma unroll
        for (int nt = 0; nt < 8; nt++) {
            int n = col0 + wn * 64 + nt * 8 + c2;
            float e0 = __expf(acc[mt][nt][0] * scale + md0);
            float e1 = __expf(acc[mt][nt][1] * scale + md0);
            float e2 = __expf(acc[mt][nt][2] * scale + md1);
            float e3 = __expf(acc[mt][nt][3] * scale + md1);
            *(float2*)&C[(size_t)m0 * Ls + n]       = make_float2(e0, e1);
            *(float2*)&C[(size_t)(m0 + 8) * Ls + n] = make_float2(e2, e3);
            cs[nt][0] += e0 + e2;
            cs[nt][1] += e1 + e3;
        }
    }
    #pragma unroll
    for (int nt = 0; nt < 8; nt++) {
        int n = col0 + wn * 64 + nt * 8 + c2;
        atomicAdd(&gsum[n],     cs[nt][0]);
        atomicAdd(&gsum[n + 1], cs[nt][1]);
    }
}

// invert column sums in place
__global__ void inv_kernel()
{
    int i = blockIdx.x * 256 + threadIdx.x;
    g_ci[i] = 1.0f / g_ci[i];
}

// heads: hd[b,l,h*128+dv] = sum_k E[q,k] * (v[k,dv]*inv[k])
__global__ void __launch_bounds__(NTHD, 2)
heads_kernel()
{
    const int bh = blockIdx.y;
    const int b  = bh >> 3;
    const int h  = bh & 7;
    const int row0 = blockIdx.x * BM;

    const float* A  = g_s + (size_t)bh * Ls * Ls;
    const float* Bm = g_v + (size_t)bh * Ls * DK;
    const float* gi = g_ci + (size_t)bh * Ls;
    float*       C  = g_hd + (size_t)b * Ls * (NH * DK) + h * DK;

    float acc[4][8][4] = {};
    gemm_main<0, 2>(A, Ls, Bm, DK, Ls, row0, 0, gi, acc);

    const int lane = threadIdx.x & 31, wid = threadIdx.x >> 5;
    const int wm = wid & 1, wn = wid >> 1;
    const int r = lane >> 2, c2 = (lane & 3) << 1;
    #pragma unroll
    for (int mt = 0; mt < 4; mt++)
        #pragma unroll
        for (int nt = 0; nt < 8; nt++) {
            int m0 = row0 + wm * 64 + mt * 16 + r;
            int n  = wn * 64 + nt * 8 + c2;
            *(float2*)&C[(size_t)m0 * (NH * DK) + n]       = make_float2(acc[mt][nt][0], acc[mt][nt][1]);
            *(float2*)&C[(size_t)(m0 + 8) * (NH * DK) + n] = make_float2(acc[mt][nt][2], acc[mt][nt][3]);
        }
}

// out: out[b, n, m] = sum_j hd[b,m,j] * Wo[j,n]  (transposed write, fused)
__global__ void __launch_bounds__(NTHD, 2)
out_kernel(const float* __restrict__ Wo, float* __restrict__ outp)
{
    const int b = blockIdx.z;
    const int row0 = blockIdx.y * BM;
    const int col0 = blockIdx.x * BN;

    const float* A = g_hd + (size_t)b * Ls * Dd;
    float*       C = outp + (size_t)b * Dd * Ls;   // [D][L]

    float acc[4][8][4] = {};
    gemm_main<0, 0>(A, Dd, Wo, Dd, Dd, row0, col0, nullptr, acc);

    const int lane = threadIdx.x & 31, wid = threadIdx.x >> 5;
    const int wm = wid & 1, wn = wid >> 1;
    const int r = lane >> 2, c2 = (lane & 3) << 1;
    #pragma unroll
    for (int mt = 0; mt < 4; mt++) {
        int m0 = row0 + wm * 64 + mt * 16 + r;
        #pragma unroll
        for (int nt = 0; nt < 8; nt++) {
            int n = col0 + wn * 64 + nt * 8 + c2;
            C[(size_t)n * Ls + m0]           = acc[mt][nt][0];
            C[(size_t)(n + 1) * Ls + m0]     = acc[mt][nt][1];
            C[(size_t)n * Ls + m0 + 8]       = acc[mt][nt][2];
            C[(size_t)(n + 1) * Ls + m0 + 8] = acc[mt][nt][3];
        }
    }
}

// -------------------- launch --------------------
extern "C" void kernel_launch(void* const* d_in, const int* in_sizes, int n_in,
                              void* d_out, int out_size)
{
    const float* x    = (const float*)d_in[0];   // [B, D, L]
    const float* mask = (const float*)d_in[1];   // [B, L]
    const float* Wq   = (const float*)d_in[2];   // [H, D, DK]
    const float* Wk   = (const float*)d_in[3];
    const float* Wv   = (const float*)d_in[4];
    const float* Wo   = (const float*)d_in[5];   // [D, H*DK]
    float* out = (float*)d_out;                  // [B, D, L]

    float* ci_ptr; cudaGetSymbolAddress((void**)&ci_ptr, g_ci);
    cudaMemsetAsync(ci_ptr, 0, (size_t)Bsz * NH * Ls * sizeof(float), 0);

    {   // QKV projections (x read transposed in-kernel)
        dim3 g(Ls / BM, NH, 3 * Bsz);
        proj_kernel<<<g, NTHD>>>(x, Wq, Wk, Wv);
    }
    {   // scores -> E = exp(...), atomic column sums
        dim3 g(Ls / BN, Ls / BM, Bsz * NH);
        scores_kernel<<<g, NTHD>>>(mask);
    }
    {   // invert column sums
        inv_kernel<<<(Bsz * NH * Ls) / 256, 256>>>();
    }
    {   // heads = E @ (V * inv)
        dim3 g(Ls / BM, Bsz * NH);
        heads_kernel<<<g, NTHD>>>();
    }
    {   // output projection with fused transpose
        dim3 g(Dd / BN, Ls / BM, Bsz);
        out_kernel<<<g, NTHD>>>(Wo, out);
    }
}